// round 5
// baseline (speedup 1.0000x reference)
#include <cuda_runtime.h>

// Decoder: 8 batches of 32-segment piecewise-linear functions sampled at
// 196608 uniform points. Output [8, 196608] fp32 = 6.29MB (L2-resident).
// Two-phase: tiny setup kernel precomputes per-block segment records so the
// main kernel has NO shared memory, NO barriers, NO searches.

#define S_TOTAL 196608
#define NB 8
#define NSEG 32
#define NP1 33
#define THREADS 256
#define ITERS 2                                     // float4s per thread
#define PIX_PER_BLOCK (THREADS * ITERS * 4)         // 2048
#define BLOCKS_PER_BATCH (S_TOTAL / PIX_PER_BLOCK)  // 96
#define NBLOCKS (NB * BLOCKS_PER_BATCH)             // 768

__device__ float  g_xs[NB][NP1];     // fixed (running-max) knots
__device__ float4 g_cf[NB][NSEG];    // per-segment {x, y, slope, pad}
__device__ float4 g_rec[NBLOCKS][2]; // per-block {xb,c0x,c0y,c0r},{fb,c1x,c1y,c1r}

// ---------------------------------------------------------------- setup ----
__global__ __launch_bounds__(256) void setup_kernel(
    const float* __restrict__ segx,
    const float* __restrict__ segy)
{
    __shared__ float  sxs[NB][NP1];
    __shared__ float4 scf[NB][NSEG];

    const int tid = threadIdx.x;
    const int w = tid >> 5;          // 8 warps, one batch each
    const int lane = tid & 31;
    const float inv = 1.0f / (float)S_TOTAL;

    // Parallel running-max scan over 33 knots (ties -> later entry wins).
    {
        const float* px = segx + w * NP1;
        const float* py = segy + w * NP1;
        const float x0v = px[0];
        const float y0v = py[0];
        float xv = px[lane + 1];
        float yv = py[lane + 1];
        #pragma unroll
        for (int d = 1; d < 32; d <<= 1) {
            float ox = __shfl_up_sync(0xffffffffu, xv, d);
            float oy = __shfl_up_sync(0xffffffffu, yv, d);
            if (lane >= d && ox > xv) { xv = ox; yv = oy; }
        }
        if (x0v > xv) { xv = x0v; yv = y0v; }       // fold in knot 0 as prefix
        float xp = __shfl_up_sync(0xffffffffu, xv, 1);
        float yp = __shfl_up_sync(0xffffffffu, yv, 1);
        if (lane == 0) { xp = x0v; yp = y0v; }
        float dd = xv - xp;
        if (dd == 0.0f) dd = 0.0001f;
        float4 c = make_float4(xp, yp, (yv - yp) / dd, 0.0f);
        sxs[w][lane] = xp;  g_xs[w][lane] = xp;
        scf[w][lane] = c;   g_cf[w][lane] = c;
        if (lane == 31) { sxs[w][32] = xv; g_xs[w][32] = xv; }
    }
    __syncthreads();

    // 768 per-block records, 3 per thread.
    #pragma unroll
    for (int k = 0; k < NBLOCKS / 256; k++) {
        const int idx = tid + k * 256;
        const int b = idx / BLOCKS_PER_BATCH;
        const int chunk = idx - b * BLOCKS_PER_BATCH;
        const int s_base = chunk * PIX_PER_BLOCK;
        const float x_lo = (float)(s_base + 1) * inv;
        const float x_hi = (float)(s_base + PIX_PER_BLOCK) * inv;
        // j = largest k in [0,31] with xs[k] <= x (handles both clamps too).
        int jl = 0, jh = 0;
        #pragma unroll
        for (int st = 16; st >= 1; st >>= 1) {
            if (sxs[b][jl + st] <= x_lo) jl += st;
            if (sxs[b][jh + st] <= x_hi) jh += st;
        }
        const float4 c0 = scf[b][jl];
        const float4 c1 = scf[b][jh];
        const float fb = (jh > jl + 1) ? 1.0f : 0.0f;  // >=2 boundaries in block
        g_rec[idx][0] = make_float4(sxs[b][jh], c0.x, c0.y, c0.z);
        g_rec[idx][1] = make_float4(fb,         c1.x, c1.y, c1.z);
    }
}

// ----------------------------------------------------------------- main ----
__global__ __launch_bounds__(THREADS) void decoder_pwl_kernel(
    float* __restrict__ out)
{
    const int blk = blockIdx.x;
    const int b = blk / BLOCKS_PER_BATCH;
    const int chunk = blk - b * BLOCKS_PER_BATCH;
    const int tid = threadIdx.x;
    const int s_base = chunk * PIX_PER_BLOCK;
    const float inv = 1.0f / (float)S_TOTAL;        // <=1ulp vs IEEE div; tol 1e-3

    const float4 recA = g_rec[blk][0];              // {xb, c0x, c0y, c0r}
    const float4 recB = g_rec[blk][1];              // {fb, c1x, c1y, c1r}

    // First pixel coordinate for this thread; later pixels add compile-time
    // constant multiples of inv (<=1ulp from exact, tolerance is 1e-3).
    const float x0 = (float)(s_base + tid * 4 + 1) * inv;

    float4* out4 = reinterpret_cast<float4*>(out);
    const int obase = b * (S_TOTAL / 4) + (s_base >> 2) + tid;

    if (recB.x == 0.0f) {
        // Common case: at most one knot boundary (xb) inside this block.
        const float xb = recA.x;
        #pragma unroll
        for (int i = 0; i < ITERS; i++) {
            float4 o;
            float* ov = &o.x;
            #pragma unroll
            for (int e = 0; e < 4; e++) {
                float xin = x0 + (float)(i * THREADS * 4 + e) * inv;
                bool hi = (xin >= xb);
                float cx = hi ? recB.y : recA.y;
                float cy = hi ? recB.z : recA.z;
                float cr = hi ? recB.w : recA.w;
                ov[e] = fmaf(cr, xin - cx, cy);     // same arith order as ref
            }
            out4[obase + i * THREADS] = o;
        }
    } else {
        // Rare: multiple knots inside this block -> per-pixel search (L1-hot).
        const float*  xs = g_xs[b];
        const float4* cf = g_cf[b];
        #pragma unroll
        for (int i = 0; i < ITERS; i++) {
            float4 o;
            float* ov = &o.x;
            #pragma unroll
            for (int e = 0; e < 4; e++) {
                float xin = x0 + (float)(i * THREADS * 4 + e) * inv;
                int j = 0;
                #pragma unroll
                for (int st = 16; st >= 1; st >>= 1) {
                    if (xs[j + st] <= xin) j += st;
                }
                float4 c = cf[j];
                ov[e] = fmaf(c.z, xin - c.x, c.y);
            }
            out4[obase + i * THREADS] = o;
        }
    }
}

extern "C" void kernel_launch(void* const* d_in, const int* in_sizes, int n_in,
                              void* d_out, int out_size) {
    const float* segx = (const float*)d_in[0];
    const float* segy = (const float*)d_in[1];
    float* out = (float*)d_out;

    setup_kernel<<<1, 256>>>(segx, segy);
    decoder_pwl_kernel<<<NBLOCKS, THREADS>>>(out);
}

// round 6
// speedup vs baseline: 1.6154x; 1.6154x over previous
#include <cuda_runtime.h>

// Decoder: 8 batches of 32-segment piecewise-linear functions sampled at
// 196608 uniform points. Output [8, 196608] fp32 = 6.29MB (L2-resident).
// Fully barrier-free: every warp rebuilds the knot table in registers via
// shuffles, locates its 256-pixel tile's (at most one) boundary, then runs a
// branchless predicated hot loop. No shared memory, no __syncthreads.

#define S_TOTAL 196608
#define NB 8
#define NSEG 32
#define NP1 33
#define THREADS 256
#define WARPS (THREADS / 32)                        // 8
#define PIX_PER_WARP 256                            // contiguous per warp
#define PIX_PER_BLOCK (WARPS * PIX_PER_WARP)        // 2048
#define BLOCKS_PER_BATCH (S_TOTAL / PIX_PER_BLOCK)  // 96
#define FULLMASK 0xffffffffu

__global__ __launch_bounds__(THREADS) void decoder_pwl_kernel(
    const float* __restrict__ segx,
    const float* __restrict__ segy,
    float* __restrict__ out)
{
    const int b = blockIdx.x / BLOCKS_PER_BATCH;
    const int chunk = blockIdx.x - b * BLOCKS_PER_BATCH;
    const int w = threadIdx.x >> 5;
    const int lane = threadIdx.x & 31;
    const float inv = 1.0f / (float)S_TOTAL;        // <=1ulp vs IEEE div; tol 1e-3

    // ---- Per-warp register-resident knot table (no smem, no barriers) ----
    // Running-max scan over 33 knots, ties -> later entry wins.
    const float* px = segx + b * NP1;
    const float* py = segy + b * NP1;
    const float x0v = px[0];                         // uniform LDG, L1-broadcast
    const float y0v = py[0];
    float xv = px[lane + 1];
    float yv = py[lane + 1];
    #pragma unroll
    for (int d = 1; d < 32; d <<= 1) {
        float ox = __shfl_up_sync(FULLMASK, xv, d);
        float oy = __shfl_up_sync(FULLMASK, yv, d);
        if (lane >= d && ox > xv) { xv = ox; yv = oy; }
    }
    if (x0v > xv) { xv = x0v; yv = y0v; }            // fold in knot 0 as prefix
    float xp = __shfl_up_sync(FULLMASK, xv, 1);      // lane l: knot X[l]
    float yp = __shfl_up_sync(FULLMASK, yv, 1);      // lane l: Y[l]
    if (lane == 0) { xp = x0v; yp = y0v; }
    float dd = xv - xp;
    if (dd == 0.0f) dd = 0.0001f;
    const float rs = (yv - yp) / dd;                 // lane l: slope of seg l

    // ---- Warp tile: contiguous 256 pixels ----
    const int sw = chunk * PIX_PER_BLOCK + w * PIX_PER_WARP;  // first pixel
    const float x_lo = (float)(sw + 1) * inv;
    const float x_hi = (float)(sw + PIX_PER_WARP) * inv;

    // Dual search over register-distributed knots (uniform src lanes):
    // j = largest l in [0,31] with X[l] <= x  (reproduces one-hot + clamps).
    int jl = 0, jh = 0;
    #pragma unroll
    for (int st = 16; st >= 1; st >>= 1) {
        float xa = __shfl_sync(FULLMASK, xp, jl + st);
        float xb_ = __shfl_sync(FULLMASK, xp, jh + st);
        if (xa  <= x_lo) jl += st;
        if (xb_ <= x_hi) jh += st;
    }

    const int s0 = sw + lane * 4;                    // this thread's 1st pixel
    const float xbase = (float)(s0 + 1) * inv;
    float4* out4 = reinterpret_cast<float4*>(out);
    const int obase = b * (S_TOTAL / 4) + (sw >> 2) + lane;

    if (jh <= jl + 1) {
        // Common case: at most one knot boundary inside this warp's tile.
        const float xb  = __shfl_sync(FULLMASK, xp, jh);
        const float c0x = __shfl_sync(FULLMASK, xp, jl);
        const float c0y = __shfl_sync(FULLMASK, yp, jl);
        const float c0r = __shfl_sync(FULLMASK, rs, jl);
        const float c1y = __shfl_sync(FULLMASK, yp, jh);
        const float c1r = __shfl_sync(FULLMASK, rs, jh);
        #pragma unroll
        for (int i = 0; i < 2; i++) {
            float4 o;
            float* ov = &o.x;
            #pragma unroll
            for (int e = 0; e < 4; e++) {
                float xin = xbase + (float)(i * 128 + e) * inv;
                bool hi = (xin >= xb);
                float cx = hi ? xb  : c0x;
                float cy = hi ? c1y : c0y;
                float cr = hi ? c1r : c0r;
                ov[e] = fmaf(cr, xin - cx, cy);      // same arith order as ref
            }
            out4[obase + i * 32] = o;
        }
    } else {
        // Rare (~0.4% of warps, warp-uniform): per-pixel shuffle search.
        #pragma unroll
        for (int i = 0; i < 2; i++) {
            float4 o;
            float* ov = &o.x;
            #pragma unroll
            for (int e = 0; e < 4; e++) {
                float xin = xbase + (float)(i * 128 + e) * inv;
                int j = 0;
                #pragma unroll
                for (int st = 16; st >= 1; st >>= 1) {
                    float xc = __shfl_sync(FULLMASK, xp, j + st);  // per-lane src
                    if (xc <= xin) j += st;
                }
                float cx = __shfl_sync(FULLMASK, xp, j);
                float cy = __shfl_sync(FULLMASK, yp, j);
                float cr = __shfl_sync(FULLMASK, rs, j);
                ov[e] = fmaf(cr, xin - cx, cy);
            }
            out4[obase + i * 32] = o;
        }
    }
}

extern "C" void kernel_launch(void* const* d_in, const int* in_sizes, int n_in,
                              void* d_out, int out_size) {
    const float* segx = (const float*)d_in[0];
    const float* segy = (const float*)d_in[1];
    float* out = (float*)d_out;

    const int blocks = NB * BLOCKS_PER_BATCH;        // 768
    decoder_pwl_kernel<<<blocks, THREADS>>>(segx, segy, out);
}